// round 2
// baseline (speedup 1.0000x reference)
#include <cuda_runtime.h>
#include <cuda_bf16.h>
#include <math.h>

// Problem constants (shapes fixed by the reference).
#define NMAX 100000
#define FD   64          // feature dim (D == H == 64)

// ---------------------------------------------------------------------------
// Scratch (no allocations allowed -> __device__ globals)
// ---------------------------------------------------------------------------
__device__ float g_z[NMAX * FD];    // transformed features (X@W) per layer
__device__ float g_h[NMAX * FD];    // aggregated layer-1 hidden
__device__ float g_dinv[NMAX];      // deg^-1/2
__device__ int   g_deg[NMAX];       // in-degree incl. self loop

// ---------------------------------------------------------------------------
// Degree / normalization
// ---------------------------------------------------------------------------
__global__ void k_deg_init(int* __restrict__ deg, int n) {
    int i = blockIdx.x * blockDim.x + threadIdx.x;
    if (i < n) deg[i] = 1;  // self loop
}

__global__ void k_deg_count(const int* __restrict__ col,
                            int* __restrict__ deg, int E) {
    int e = blockIdx.x * blockDim.x + threadIdx.x;
    if (e < E) atomicAdd(&deg[col[e]], 1);
}

__global__ void k_dinv(const int* __restrict__ deg,
                       float* __restrict__ dinv, int n) {
    int i = blockIdx.x * blockDim.x + threadIdx.x;
    if (i < n) dinv[i] = rsqrtf((float)deg[i]);
}

// ---------------------------------------------------------------------------
// GEMM: Z[n,64] = act(X[n,64]) @ W[64,64]
//   RELU applied to the INPUT rows when loading (layer 2 consumes relu(h1)).
//   Block: 256 threads, 32 rows per block. Full W (16 KB) + X tile (8 KB) in smem.
// ---------------------------------------------------------------------------
template <bool RELU_IN>
__global__ void k_gemm64(const float* __restrict__ X,
                         const float* __restrict__ W,
                         float* __restrict__ Z, int n) {
    __shared__ float Ws[64][64];
    __shared__ float Xs[32][64];
    int t = threadIdx.x;

    #pragma unroll
    for (int i = t; i < 64 * 64; i += 256) Ws[i >> 6][i & 63] = W[i];

    int r0 = blockIdx.x * 32;
    #pragma unroll
    for (int i = t; i < 32 * 64; i += 256) {
        int r = r0 + (i >> 6);
        float v = (r < n) ? X[(size_t)r * FD + (i & 63)] : 0.0f;
        if (RELU_IN) v = fmaxf(v, 0.0f);
        Xs[i >> 6][i & 63] = v;
    }
    __syncthreads();

    int col = t & 63;
    int rb  = t >> 6;  // 0..3
    float acc[8] = {0.f, 0.f, 0.f, 0.f, 0.f, 0.f, 0.f, 0.f};

    #pragma unroll
    for (int k = 0; k < 64; k++) {
        float wv = Ws[k][col];
        #pragma unroll
        for (int rr = 0; rr < 8; rr++)
            acc[rr] = fmaf(Xs[rb + rr * 4][k], wv, acc[rr]);
    }

    #pragma unroll
    for (int rr = 0; rr < 8; rr++) {
        int r = r0 + rb + rr * 4;
        if (r < n) Z[(size_t)r * FD + col] = acc[rr];
    }
}

// ---------------------------------------------------------------------------
// Accumulator init: h[i,:] = z[i,:] * dinv[i]^2 (self loop) + bias
// ---------------------------------------------------------------------------
__global__ void k_init_acc(const float* __restrict__ z,
                           const float* __restrict__ dinv,
                           const float* __restrict__ bias,
                           float* __restrict__ h, int n) {
    int i = blockIdx.x * blockDim.x + threadIdx.x;
    int total = n * FD;
    if (i >= total) return;
    int node = i >> 6, j = i & 63;
    float d = dinv[node];
    h[i] = z[i] * d * d + bias[j];
}

// ---------------------------------------------------------------------------
// Edge aggregation: for each edge e: h[col[e],:] += z[row[e],:] * norm(e)
//   16 threads per edge, float4 per thread -> one 256B coalesced segment per
//   edge for both the gather and the vector reduction (red.global.add.v4.f32).
// ---------------------------------------------------------------------------
__global__ void k_edge_agg(const int* __restrict__ row,
                           const int* __restrict__ col,
                           const float* __restrict__ dinv,
                           const float* __restrict__ z,
                           float* __restrict__ h, int E) {
    long long tid = (long long)blockIdx.x * blockDim.x + threadIdx.x;
    int e = (int)(tid >> 4);
    int j = (int)(tid & 15);
    if (e >= E) return;

    int r = row[e];
    int c = col[e];
    float nrm = dinv[r] * dinv[c];

    const float4 v = *reinterpret_cast<const float4*>(z + (size_t)r * FD + j * 4);
    float a = v.x * nrm, b = v.y * nrm, cc = v.z * nrm, d = v.w * nrm;

    float* p = h + (size_t)c * FD + j * 4;
    asm volatile("red.global.add.v4.f32 [%0], {%1, %2, %3, %4};"
                 :: "l"(p), "f"(a), "f"(b), "f"(cc), "f"(d)
                 : "memory");
}

// ---------------------------------------------------------------------------
// Final in-place relu on the output
// ---------------------------------------------------------------------------
__global__ void k_relu(float* __restrict__ h, int total) {
    int i = blockIdx.x * blockDim.x + threadIdx.x;
    if (i < total) h[i] = fmaxf(h[i], 0.0f);
}

// ---------------------------------------------------------------------------
// Launch
//   Inputs (metadata order): x [N*64] f32, edge_index [2*E] int32 (harness
//   downcasts int64 -> int32), W1 [64*64] f32, b1 [64] f32, W2 [64*64] f32,
//   b2 [64] f32. Output: [N*64] f32.
// ---------------------------------------------------------------------------
extern "C" void kernel_launch(void* const* d_in, const int* in_sizes, int n_in,
                              void* d_out, int out_size) {
    const float* x  = (const float*)d_in[0];
    const int*   ei = (const int*)d_in[1];
    const float* W1 = (const float*)d_in[2];
    const float* b1 = (const float*)d_in[3];
    const float* W2 = (const float*)d_in[4];
    const float* b2 = (const float*)d_in[5];
    float*       out = (float*)d_out;

    const int n = in_sizes[0] / FD;        // 100000
    const int E = in_sizes[1] / 2;         // 1000000
    const int* row = ei;
    const int* col = ei + E;

    float* z = nullptr; float* h = nullptr; float* dinv = nullptr; int* deg = nullptr;
    cudaGetSymbolAddress((void**)&z,    g_z);
    cudaGetSymbolAddress((void**)&h,    g_h);
    cudaGetSymbolAddress((void**)&dinv, g_dinv);
    cudaGetSymbolAddress((void**)&deg,  g_deg);

    const int T = 256;
    const int gN    = (n + T - 1) / T;
    const int gE    = (E + T - 1) / T;
    const int gNF   = (n * FD + T - 1) / T;
    const int gEdge = (int)(((long long)E * 16 + T - 1) / T);
    const int gGemm = (n + 31) / 32;

    // normalization
    k_deg_init <<<gN, T>>>(deg, n);
    k_deg_count<<<gE, T>>>(col, deg, E);
    k_dinv     <<<gN, T>>>(deg, dinv, n);

    // layer 1
    k_gemm64<false><<<gGemm, T>>>(x, W1, z, n);
    k_init_acc     <<<gNF, T>>>(z, dinv, b1, h, n);
    k_edge_agg     <<<gEdge, T>>>(row, col, dinv, z, h, E);

    // layer 2 (relu of h fused into gemm input load)
    k_gemm64<true><<<gGemm, T>>>(h, W2, z, n);
    k_init_acc    <<<gNF, T>>>(z, dinv, b2, out, n);
    k_edge_agg    <<<gEdge, T>>>(row, col, dinv, z, out, E);
    k_relu        <<<gNF, T>>>(out, n * FD);
}

// round 3
// speedup vs baseline: 1.0033x; 1.0033x over previous
#include <cuda_runtime.h>
#include <cuda_bf16.h>
#include <math.h>

// Problem constants (shapes fixed by the reference).
#define NMAX 100000
#define FD   64          // feature dim (D == H == 64)

// ---------------------------------------------------------------------------
// Scratch (no allocations allowed -> __device__ globals)
// ---------------------------------------------------------------------------
__device__ float g_z[NMAX * FD];    // transformed features (X@W) per layer
__device__ float g_h[NMAX * FD];    // aggregated layer-1 hidden
__device__ float g_dinv[NMAX];      // deg^-1/2
__device__ int   g_deg[NMAX];       // in-degree incl. self loop

// ---------------------------------------------------------------------------
// Degree / normalization
// ---------------------------------------------------------------------------
__global__ void k_deg_init(int* __restrict__ deg, int n) {
    int i = blockIdx.x * blockDim.x + threadIdx.x;
    if (i < n) deg[i] = 1;  // self loop
}

__global__ void k_deg_count(const int* __restrict__ col,
                            int* __restrict__ deg, int E) {
    int e = blockIdx.x * blockDim.x + threadIdx.x;
    if (e < E) atomicAdd(&deg[col[e]], 1);
}

__global__ void k_dinv(const int* __restrict__ deg,
                       float* __restrict__ dinv, int n) {
    int i = blockIdx.x * blockDim.x + threadIdx.x;
    if (i < n) dinv[i] = rsqrtf((float)deg[i]);
}

// ---------------------------------------------------------------------------
// GEMM: Z[n,64] = act(X[n,64]) @ W[64,64]
//   RELU applied to the INPUT rows when loading (layer 2 consumes relu(h1)).
//   Block: 256 threads, 32 rows per block. Full W (16 KB) + X tile (8 KB) in smem.
// ---------------------------------------------------------------------------
template <bool RELU_IN>
__global__ void k_gemm64(const float* __restrict__ X,
                         const float* __restrict__ W,
                         float* __restrict__ Z, int n) {
    __shared__ float Ws[64][64];
    __shared__ float Xs[32][64];
    int t = threadIdx.x;

    #pragma unroll
    for (int i = t; i < 64 * 64; i += 256) Ws[i >> 6][i & 63] = W[i];

    int r0 = blockIdx.x * 32;
    #pragma unroll
    for (int i = t; i < 32 * 64; i += 256) {
        int r = r0 + (i >> 6);
        float v = (r < n) ? X[(size_t)r * FD + (i & 63)] : 0.0f;
        if (RELU_IN) v = fmaxf(v, 0.0f);
        Xs[i >> 6][i & 63] = v;
    }
    __syncthreads();

    int col = t & 63;
    int rb  = t >> 6;  // 0..3
    float acc[8] = {0.f, 0.f, 0.f, 0.f, 0.f, 0.f, 0.f, 0.f};

    #pragma unroll
    for (int k = 0; k < 64; k++) {
        float wv = Ws[k][col];
        #pragma unroll
        for (int rr = 0; rr < 8; rr++)
            acc[rr] = fmaf(Xs[rb + rr * 4][k], wv, acc[rr]);
    }

    #pragma unroll
    for (int rr = 0; rr < 8; rr++) {
        int r = r0 + rb + rr * 4;
        if (r < n) Z[(size_t)r * FD + col] = acc[rr];
    }
}

// ---------------------------------------------------------------------------
// Accumulator init: h[i,:] = z[i,:] * dinv[i]^2 (self loop) + bias
// ---------------------------------------------------------------------------
__global__ void k_init_acc(const float* __restrict__ z,
                           const float* __restrict__ dinv,
                           const float* __restrict__ bias,
                           float* __restrict__ h, int n) {
    int i = blockIdx.x * blockDim.x + threadIdx.x;
    int total = n * FD;
    if (i >= total) return;
    int node = i >> 6, j = i & 63;
    float d = dinv[node];
    h[i] = z[i] * d * d + bias[j];
}

// ---------------------------------------------------------------------------
// Edge aggregation: for each edge e: h[col[e],:] += z[row[e],:] * norm(e)
//   16 threads per edge, float4 per thread -> one 256B coalesced segment per
//   edge for both the gather and the vector reduction (red.global.add.v4.f32).
// ---------------------------------------------------------------------------
__global__ void k_edge_agg(const int* __restrict__ row,
                           const int* __restrict__ col,
                           const float* __restrict__ dinv,
                           const float* __restrict__ z,
                           float* __restrict__ h, int E) {
    long long tid = (long long)blockIdx.x * blockDim.x + threadIdx.x;
    int e = (int)(tid >> 4);
    int j = (int)(tid & 15);
    if (e >= E) return;

    int r = row[e];
    int c = col[e];
    float nrm = dinv[r] * dinv[c];

    const float4 v = *reinterpret_cast<const float4*>(z + (size_t)r * FD + j * 4);
    float a = v.x * nrm, b = v.y * nrm, cc = v.z * nrm, d = v.w * nrm;

    float* p = h + (size_t)c * FD + j * 4;
    asm volatile("red.global.add.v4.f32 [%0], {%1, %2, %3, %4};"
                 :: "l"(p), "f"(a), "f"(b), "f"(cc), "f"(d)
                 : "memory");
}

// ---------------------------------------------------------------------------
// Final in-place relu on the output
// ---------------------------------------------------------------------------
__global__ void k_relu(float* __restrict__ h, int total) {
    int i = blockIdx.x * blockDim.x + threadIdx.x;
    if (i < total) h[i] = fmaxf(h[i], 0.0f);
}

// ---------------------------------------------------------------------------
// Launch
//   Inputs (metadata order): x [N*64] f32, edge_index [2*E] int32 (harness
//   downcasts int64 -> int32), W1 [64*64] f32, b1 [64] f32, W2 [64*64] f32,
//   b2 [64] f32. Output: [N*64] f32.
// ---------------------------------------------------------------------------
extern "C" void kernel_launch(void* const* d_in, const int* in_sizes, int n_in,
                              void* d_out, int out_size) {
    const float* x  = (const float*)d_in[0];
    const int*   ei = (const int*)d_in[1];
    const float* W1 = (const float*)d_in[2];
    const float* b1 = (const float*)d_in[3];
    const float* W2 = (const float*)d_in[4];
    const float* b2 = (const float*)d_in[5];
    float*       out = (float*)d_out;

    const int n = in_sizes[0] / FD;        // 100000
    const int E = in_sizes[1] / 2;         // 1000000
    const int* row = ei;
    const int* col = ei + E;

    float* z = nullptr; float* h = nullptr; float* dinv = nullptr; int* deg = nullptr;
    cudaGetSymbolAddress((void**)&z,    g_z);
    cudaGetSymbolAddress((void**)&h,    g_h);
    cudaGetSymbolAddress((void**)&dinv, g_dinv);
    cudaGetSymbolAddress((void**)&deg,  g_deg);

    const int T = 256;
    const int gN    = (n + T - 1) / T;
    const int gE    = (E + T - 1) / T;
    const int gNF   = (n * FD + T - 1) / T;
    const int gEdge = (int)(((long long)E * 16 + T - 1) / T);
    const int gGemm = (n + 31) / 32;

    // normalization
    k_deg_init <<<gN, T>>>(deg, n);
    k_deg_count<<<gE, T>>>(col, deg, E);
    k_dinv     <<<gN, T>>>(deg, dinv, n);

    // layer 1
    k_gemm64<false><<<gGemm, T>>>(x, W1, z, n);
    k_init_acc     <<<gNF, T>>>(z, dinv, b1, h, n);
    k_edge_agg     <<<gEdge, T>>>(row, col, dinv, z, h, E);

    // layer 2 (relu of h fused into gemm input load)
    k_gemm64<true><<<gGemm, T>>>(h, W2, z, n);
    k_init_acc    <<<gNF, T>>>(z, dinv, b2, out, n);
    k_edge_agg    <<<gEdge, T>>>(row, col, dinv, z, out, E);
    k_relu        <<<gNF, T>>>(out, n * FD);
}

// round 4
// speedup vs baseline: 1.6213x; 1.6159x over previous
#include <cuda_runtime.h>
#include <cuda_bf16.h>
#include <math.h>

#define NMAX 100000
#define FD   64

// ---------------------------------------------------------------------------
// Scratch (__device__ globals; no allocation allowed)
// ---------------------------------------------------------------------------
__device__ float g_z[NMAX * FD];      // dinv-scaled transformed features
__device__ float g_h[NMAX * FD];      // layer-1 output (relu'd)
__device__ float g_dinv[NMAX];
__device__ int   g_cnt[NMAX];         // in-degree (edges only)
__device__ int   g_start[NMAX];       // CSR row start (exclusive scan of cnt)
__device__ int   g_cursor[NMAX];      // fill cursors
__device__ int   g_srcs[1100000];     // CSR: source node per incoming edge
__device__ int   g_bsum[1024];        // scan block sums

// ---------------------------------------------------------------------------
// Degree / normalization
// ---------------------------------------------------------------------------
__global__ void k_count(const int* __restrict__ col, int* __restrict__ cnt, int E) {
    int e = blockIdx.x * blockDim.x + threadIdx.x;
    if (e < E) atomicAdd(&cnt[col[e]], 1);
}

__global__ void k_dinv(const int* __restrict__ cnt, float* __restrict__ dinv, int n) {
    int i = blockIdx.x * blockDim.x + threadIdx.x;
    if (i < n) dinv[i] = rsqrtf((float)(cnt[i] + 1));   // + self loop
}

// ---------------------------------------------------------------------------
// Exclusive prefix sum of cnt -> start (3-phase block scan)
// ---------------------------------------------------------------------------
__global__ void k_scan1(const int* __restrict__ cnt, int* __restrict__ startv,
                        int* __restrict__ bsum, int n) {
    __shared__ int sh[256];
    int t = threadIdx.x, i = blockIdx.x * 256 + t;
    int v = (i < n) ? cnt[i] : 0;
    sh[t] = v; __syncthreads();
    #pragma unroll
    for (int off = 1; off < 256; off <<= 1) {
        int x = (t >= off) ? sh[t - off] : 0;
        __syncthreads();
        sh[t] += x;
        __syncthreads();
    }
    if (i < n) startv[i] = sh[t] - v;           // block-local exclusive
    if (t == 255) bsum[blockIdx.x] = sh[255];   // block total
}

__global__ void k_scan2(int* __restrict__ bsum, int nb) {
    __shared__ int sh[512];
    int t = threadIdx.x;
    int v = (t < nb) ? bsum[t] : 0;
    sh[t] = v; __syncthreads();
    #pragma unroll
    for (int off = 1; off < 512; off <<= 1) {
        int x = (t >= off) ? sh[t - off] : 0;
        __syncthreads();
        sh[t] += x;
        __syncthreads();
    }
    if (t < nb) bsum[t] = sh[t] - v;            // exclusive
}

__global__ void k_scan3(int* __restrict__ startv, int* __restrict__ cursor,
                        const int* __restrict__ bsum, int n) {
    int i = blockIdx.x * blockDim.x + threadIdx.x;
    if (i < n) {
        int s = startv[i] + bsum[i >> 8];
        startv[i] = s;
        cursor[i] = s;
    }
}

__global__ void k_fill(const int* __restrict__ row, const int* __restrict__ col,
                       int* __restrict__ cursor, int* __restrict__ srcs, int E) {
    int e = blockIdx.x * blockDim.x + threadIdx.x;
    if (e < E) {
        int pos = atomicAdd(&cursor[col[e]], 1);
        srcs[pos] = row[e];
    }
}

// ---------------------------------------------------------------------------
// GEMM: Zs[r,:] = (X[r,:] @ W) * dinv[r]
//   64x64 block tile, 256 threads, 4x4 register tile/thread.
//   X tile stored k-major (transposed) in smem -> 2 LDS.128 per 16 FMA.
// ---------------------------------------------------------------------------
__global__ void k_gemm64(const float* __restrict__ X,
                         const float* __restrict__ W,
                         const float* __restrict__ dinv,
                         float* __restrict__ Z, int n) {
    __shared__ float Ws[64][64];     // Ws[k][col]
    __shared__ float Xst[64][68];    // Xst[k][row]  (stride 68: 16B-aligned quads)
    int t = threadIdx.x;
    int r0 = blockIdx.x * 64;

    #pragma unroll
    for (int i = t; i < 64 * 64; i += 256) Ws[i >> 6][i & 63] = W[i];

    #pragma unroll
    for (int q = t; q < 1024; q += 256) {       // 64 rows x 16 quads
        int r  = q >> 4;
        int c4 = (q & 15) * 4;
        int gr = r0 + r;
        float4 v = (gr < n) ? *reinterpret_cast<const float4*>(X + (size_t)gr * FD + c4)
                            : make_float4(0.f, 0.f, 0.f, 0.f);
        Xst[c4 + 0][r] = v.x; Xst[c4 + 1][r] = v.y;
        Xst[c4 + 2][r] = v.z; Xst[c4 + 3][r] = v.w;
    }
    __syncthreads();

    int tx = t & 15, ty = t >> 4;               // cols tx*4.., rows ty*4..
    float acc[4][4] = {};

    #pragma unroll
    for (int k = 0; k < 64; k++) {
        float4 xv = *reinterpret_cast<const float4*>(&Xst[k][ty * 4]);
        float4 wv = *reinterpret_cast<const float4*>(&Ws[k][tx * 4]);
        float xr[4] = {xv.x, xv.y, xv.z, xv.w};
        float wc[4] = {wv.x, wv.y, wv.z, wv.w};
        #pragma unroll
        for (int i = 0; i < 4; i++)
            #pragma unroll
            for (int j = 0; j < 4; j++)
                acc[i][j] = fmaf(xr[i], wc[j], acc[i][j]);
    }

    #pragma unroll
    for (int i = 0; i < 4; i++) {
        int gr = r0 + ty * 4 + i;
        if (gr < n) {
            float s = dinv[gr];
            float4 o = make_float4(acc[i][0] * s, acc[i][1] * s,
                                   acc[i][2] * s, acc[i][3] * s);
            *reinterpret_cast<float4*>(Z + (size_t)gr * FD + tx * 4) = o;
        }
    }
}

// ---------------------------------------------------------------------------
// Pull aggregation: out[c,:] = relu( (zs[c,:] + sum_{r->c} zs[r,:]) * dinv[c] + b )
//   One warp per node; float2 per lane; edge loop unrolled x4 for MLP.
// ---------------------------------------------------------------------------
__global__ void k_agg(const float* __restrict__ zs,
                      const int* __restrict__ srcs,
                      const int* __restrict__ startv,
                      const int* __restrict__ cnt,
                      const float* __restrict__ dinv,
                      const float* __restrict__ bias,
                      float* __restrict__ outp, int n) {
    int warp = (blockIdx.x * blockDim.x + threadIdx.x) >> 5;
    if (warp >= n) return;
    int lane = threadIdx.x & 31;

    const float2* zz = reinterpret_cast<const float2*>(zs);
    int s = startv[warp];
    int m = cnt[warp];
    float d = dinv[warp];

    float2 acc = zz[(size_t)warp * 32 + lane];          // self loop (zs = dinv*z)

    int i = 0;
    for (; i + 4 <= m; i += 4) {
        int r0 = srcs[s + i + 0];
        int r1 = srcs[s + i + 1];
        int r2 = srcs[s + i + 2];
        int r3 = srcs[s + i + 3];
        float2 v0 = zz[(size_t)r0 * 32 + lane];
        float2 v1 = zz[(size_t)r1 * 32 + lane];
        float2 v2 = zz[(size_t)r2 * 32 + lane];
        float2 v3 = zz[(size_t)r3 * 32 + lane];
        acc.x += (v0.x + v1.x) + (v2.x + v3.x);
        acc.y += (v0.y + v1.y) + (v2.y + v3.y);
    }
    for (; i < m; i++) {
        int r = srcs[s + i];
        float2 v = zz[(size_t)r * 32 + lane];
        acc.x += v.x; acc.y += v.y;
    }

    float2 b = reinterpret_cast<const float2*>(bias)[lane];
    float ox = fmaxf(fmaf(acc.x, d, b.x), 0.0f);
    float oy = fmaxf(fmaf(acc.y, d, b.y), 0.0f);
    reinterpret_cast<float2*>(outp)[(size_t)warp * 32 + lane] = make_float2(ox, oy);
}

// ---------------------------------------------------------------------------
// Launch
// ---------------------------------------------------------------------------
extern "C" void kernel_launch(void* const* d_in, const int* in_sizes, int n_in,
                              void* d_out, int out_size) {
    const float* x  = (const float*)d_in[0];
    const int*   ei = (const int*)d_in[1];
    const float* W1 = (const float*)d_in[2];
    const float* b1 = (const float*)d_in[3];
    const float* W2 = (const float*)d_in[4];
    const float* b2 = (const float*)d_in[5];
    float*       out = (float*)d_out;

    const int n = in_sizes[0] / FD;     // 100000
    const int E = in_sizes[1] / 2;      // 1000000
    const int* row = ei;
    const int* col = ei + E;

    float *z, *h, *dinv;
    int *cnt, *startv, *cursor, *srcs, *bsum;
    cudaGetSymbolAddress((void**)&z,      g_z);
    cudaGetSymbolAddress((void**)&h,      g_h);
    cudaGetSymbolAddress((void**)&dinv,   g_dinv);
    cudaGetSymbolAddress((void**)&cnt,    g_cnt);
    cudaGetSymbolAddress((void**)&startv, g_start);
    cudaGetSymbolAddress((void**)&cursor, g_cursor);
    cudaGetSymbolAddress((void**)&srcs,   g_srcs);
    cudaGetSymbolAddress((void**)&bsum,   g_bsum);

    const int T = 256;
    const int gN    = (n + T - 1) / T;          // 391
    const int gE    = (E + T - 1) / T;
    const int gGemm = (n + 63) / 64;
    const int gAgg  = (int)(((long long)n * 32 + T - 1) / T);

    // --- CSR build + normalization (once; reused by both layers) ---
    cudaMemsetAsync(cnt, 0, n * sizeof(int));
    k_count<<<gE, T>>>(col, cnt, E);
    k_dinv <<<gN, T>>>(cnt, dinv, n);
    k_scan1<<<gN, T>>>(cnt, startv, bsum, n);
    k_scan2<<<1, 512>>>(bsum, gN);
    k_scan3<<<gN, T>>>(startv, cursor, bsum, n);
    k_fill <<<gE, T>>>(row, col, cursor, srcs, E);

    // --- layer 1 ---
    k_gemm64<<<gGemm, T>>>(x, W1, dinv, z, n);
    k_agg   <<<gAgg, T>>>(z, srcs, startv, cnt, dinv, b1, h, n);

    // --- layer 2 ---
    k_gemm64<<<gGemm, T>>>(h, W2, dinv, z, n);
    k_agg   <<<gAgg, T>>>(z, srcs, startv, cnt, dinv, b2, out, n);
}

// round 5
// speedup vs baseline: 1.6253x; 1.0025x over previous
#include <cuda_runtime.h>
#include <cuda_bf16.h>
#include <math.h>

#define NMAX 100000
#define FD   64

// ---------------------------------------------------------------------------
// Scratch (__device__ globals; no allocation allowed)
// ---------------------------------------------------------------------------
__device__ float g_z[NMAX * FD];      // dinv-scaled transformed features
__device__ float g_h[NMAX * FD];      // layer-1 output (relu'd)
__device__ float g_dinv[NMAX];
__device__ int   g_cnt[NMAX];         // in-degree (edges only)
__device__ int   g_start[NMAX];       // CSR row start (exclusive scan of cnt)
__device__ int   g_cursor[NMAX];      // fill cursors
__device__ int   g_srcs[1100000];     // CSR: source node per incoming edge
__device__ int   g_bsum[1024];        // scan block sums

// ---------------------------------------------------------------------------
// Degree / normalization
// ---------------------------------------------------------------------------
__global__ void k_count(const int* __restrict__ col, int* __restrict__ cnt, int E) {
    int e = blockIdx.x * blockDim.x + threadIdx.x;
    if (e < E) atomicAdd(&cnt[col[e]], 1);
}

__global__ void k_dinv(const int* __restrict__ cnt, float* __restrict__ dinv, int n) {
    int i = blockIdx.x * blockDim.x + threadIdx.x;
    if (i < n) dinv[i] = rsqrtf((float)(cnt[i] + 1));   // + self loop
}

// ---------------------------------------------------------------------------
// Exclusive prefix sum of cnt -> start (3-phase block scan)
// ---------------------------------------------------------------------------
__global__ void k_scan1(const int* __restrict__ cnt, int* __restrict__ startv,
                        int* __restrict__ bsum, int n) {
    __shared__ int sh[256];
    int t = threadIdx.x, i = blockIdx.x * 256 + t;
    int v = (i < n) ? cnt[i] : 0;
    sh[t] = v; __syncthreads();
    #pragma unroll
    for (int off = 1; off < 256; off <<= 1) {
        int x = (t >= off) ? sh[t - off] : 0;
        __syncthreads();
        sh[t] += x;
        __syncthreads();
    }
    if (i < n) startv[i] = sh[t] - v;           // block-local exclusive
    if (t == 255) bsum[blockIdx.x] = sh[255];   // block total
}

__global__ void k_scan2(int* __restrict__ bsum, int nb) {
    __shared__ int sh[512];
    int t = threadIdx.x;
    int v = (t < nb) ? bsum[t] : 0;
    sh[t] = v; __syncthreads();
    #pragma unroll
    for (int off = 1; off < 512; off <<= 1) {
        int x = (t >= off) ? sh[t - off] : 0;
        __syncthreads();
        sh[t] += x;
        __syncthreads();
    }
    if (t < nb) bsum[t] = sh[t] - v;            // exclusive
}

__global__ void k_scan3(int* __restrict__ startv, int* __restrict__ cursor,
                        const int* __restrict__ bsum, int n) {
    int i = blockIdx.x * blockDim.x + threadIdx.x;
    if (i < n) {
        int s = startv[i] + bsum[i >> 8];
        startv[i] = s;
        cursor[i] = s;
    }
}

__global__ void k_fill(const int* __restrict__ row, const int* __restrict__ col,
                       int* __restrict__ cursor, int* __restrict__ srcs, int E) {
    int e = blockIdx.x * blockDim.x + threadIdx.x;
    if (e < E) {
        int pos = atomicAdd(&cursor[col[e]], 1);
        srcs[pos] = row[e];
    }
}

// ---------------------------------------------------------------------------
// GEMM: Zs[r,:] = (X[r,:] @ W) * dinv[r]
//   64x64 block tile, 256 threads, 4x4 register tile/thread.
//   X tile stored k-major (transposed) in smem -> 2 LDS.128 per 16 FMA.
// ---------------------------------------------------------------------------
__global__ void k_gemm64(const float* __restrict__ X,
                         const float* __restrict__ W,
                         const float* __restrict__ dinv,
                         float* __restrict__ Z, int n) {
    __shared__ float Ws[64][64];     // Ws[k][col]
    __shared__ float Xst[64][68];    // Xst[k][row]  (stride 68: 16B-aligned quads)
    int t = threadIdx.x;
    int r0 = blockIdx.x * 64;

    #pragma unroll
    for (int i = t; i < 64 * 64; i += 256) Ws[i >> 6][i & 63] = W[i];

    #pragma unroll
    for (int q = t; q < 1024; q += 256) {       // 64 rows x 16 quads
        int r  = q >> 4;
        int c4 = (q & 15) * 4;
        int gr = r0 + r;
        float4 v = (gr < n) ? *reinterpret_cast<const float4*>(X + (size_t)gr * FD + c4)
                            : make_float4(0.f, 0.f, 0.f, 0.f);
        Xst[c4 + 0][r] = v.x; Xst[c4 + 1][r] = v.y;
        Xst[c4 + 2][r] = v.z; Xst[c4 + 3][r] = v.w;
    }
    __syncthreads();

    int tx = t & 15, ty = t >> 4;               // cols tx*4.., rows ty*4..
    float acc[4][4] = {};

    #pragma unroll
    for (int k = 0; k < 64; k++) {
        float4 xv = *reinterpret_cast<const float4*>(&Xst[k][ty * 4]);
        float4 wv = *reinterpret_cast<const float4*>(&Ws[k][tx * 4]);
        float xr[4] = {xv.x, xv.y, xv.z, xv.w};
        float wc[4] = {wv.x, wv.y, wv.z, wv.w};
        #pragma unroll
        for (int i = 0; i < 4; i++)
            #pragma unroll
            for (int j = 0; j < 4; j++)
                acc[i][j] = fmaf(xr[i], wc[j], acc[i][j]);
    }

    #pragma unroll
    for (int i = 0; i < 4; i++) {
        int gr = r0 + ty * 4 + i;
        if (gr < n) {
            float s = dinv[gr];
            float4 o = make_float4(acc[i][0] * s, acc[i][1] * s,
                                   acc[i][2] * s, acc[i][3] * s);
            *reinterpret_cast<float4*>(Z + (size_t)gr * FD + tx * 4) = o;
        }
    }
}

// ---------------------------------------------------------------------------
// Pull aggregation: out[c,:] = relu( (zs[c,:] + sum_{r->c} zs[r,:]) * dinv[c] + b )
//   One warp per node; float2 per lane; edge loop unrolled x4 for MLP.
// ---------------------------------------------------------------------------
__global__ void k_agg(const float* __restrict__ zs,
                      const int* __restrict__ srcs,
                      const int* __restrict__ startv,
                      const int* __restrict__ cnt,
                      const float* __restrict__ dinv,
                      const float* __restrict__ bias,
                      float* __restrict__ outp, int n) {
    int warp = (blockIdx.x * blockDim.x + threadIdx.x) >> 5;
    if (warp >= n) return;
    int lane = threadIdx.x & 31;

    const float2* zz = reinterpret_cast<const float2*>(zs);
    int s = startv[warp];
    int m = cnt[warp];
    float d = dinv[warp];

    float2 acc = zz[(size_t)warp * 32 + lane];          // self loop (zs = dinv*z)

    int i = 0;
    for (; i + 4 <= m; i += 4) {
        int r0 = srcs[s + i + 0];
        int r1 = srcs[s + i + 1];
        int r2 = srcs[s + i + 2];
        int r3 = srcs[s + i + 3];
        float2 v0 = zz[(size_t)r0 * 32 + lane];
        float2 v1 = zz[(size_t)r1 * 32 + lane];
        float2 v2 = zz[(size_t)r2 * 32 + lane];
        float2 v3 = zz[(size_t)r3 * 32 + lane];
        acc.x += (v0.x + v1.x) + (v2.x + v3.x);
        acc.y += (v0.y + v1.y) + (v2.y + v3.y);
    }
    for (; i < m; i++) {
        int r = srcs[s + i];
        float2 v = zz[(size_t)r * 32 + lane];
        acc.x += v.x; acc.y += v.y;
    }

    float2 b = reinterpret_cast<const float2*>(bias)[lane];
    float ox = fmaxf(fmaf(acc.x, d, b.x), 0.0f);
    float oy = fmaxf(fmaf(acc.y, d, b.y), 0.0f);
    reinterpret_cast<float2*>(outp)[(size_t)warp * 32 + lane] = make_float2(ox, oy);
}

// ---------------------------------------------------------------------------
// Launch
// ---------------------------------------------------------------------------
extern "C" void kernel_launch(void* const* d_in, const int* in_sizes, int n_in,
                              void* d_out, int out_size) {
    const float* x  = (const float*)d_in[0];
    const int*   ei = (const int*)d_in[1];
    const float* W1 = (const float*)d_in[2];
    const float* b1 = (const float*)d_in[3];
    const float* W2 = (const float*)d_in[4];
    const float* b2 = (const float*)d_in[5];
    float*       out = (float*)d_out;

    const int n = in_sizes[0] / FD;     // 100000
    const int E = in_sizes[1] / 2;      // 1000000
    const int* row = ei;
    const int* col = ei + E;

    float *z, *h, *dinv;
    int *cnt, *startv, *cursor, *srcs, *bsum;
    cudaGetSymbolAddress((void**)&z,      g_z);
    cudaGetSymbolAddress((void**)&h,      g_h);
    cudaGetSymbolAddress((void**)&dinv,   g_dinv);
    cudaGetSymbolAddress((void**)&cnt,    g_cnt);
    cudaGetSymbolAddress((void**)&startv, g_start);
    cudaGetSymbolAddress((void**)&cursor, g_cursor);
    cudaGetSymbolAddress((void**)&srcs,   g_srcs);
    cudaGetSymbolAddress((void**)&bsum,   g_bsum);

    const int T = 256;
    const int gN    = (n + T - 1) / T;          // 391
    const int gE    = (E + T - 1) / T;
    const int gGemm = (n + 63) / 64;
    const int gAgg  = (int)(((long long)n * 32 + T - 1) / T);

    // --- CSR build + normalization (once; reused by both layers) ---
    cudaMemsetAsync(cnt, 0, n * sizeof(int));
    k_count<<<gE, T>>>(col, cnt, E);
    k_dinv <<<gN, T>>>(cnt, dinv, n);
    k_scan1<<<gN, T>>>(cnt, startv, bsum, n);
    k_scan2<<<1, 512>>>(bsum, gN);
    k_scan3<<<gN, T>>>(startv, cursor, bsum, n);
    k_fill <<<gE, T>>>(row, col, cursor, srcs, E);

    // --- layer 1 ---
    k_gemm64<<<gGemm, T>>>(x, W1, dinv, z, n);
    k_agg   <<<gAgg, T>>>(z, srcs, startv, cnt, dinv, b1, h, n);

    // --- layer 2 ---
    k_gemm64<<<gGemm, T>>>(h, W2, dinv, z, n);
    k_agg   <<<gAgg, T>>>(z, srcs, startv, cnt, dinv, b2, out, n);
}

// round 6
// speedup vs baseline: 1.6294x; 1.0025x over previous
#include <cuda_runtime.h>
#include <cuda_bf16.h>
#include <math.h>

#define NMAX 100000
#define FD   64

// ---------------------------------------------------------------------------
// Scratch (__device__ globals; no allocation allowed)
// ---------------------------------------------------------------------------
__device__ float g_z[NMAX * FD];      // dinv-scaled transformed features
__device__ float g_h[NMAX * FD];      // layer-1 output (relu'd)
__device__ float g_dinv[NMAX];
__device__ int   g_cnt[NMAX];         // in-degree (edges only)
__device__ int   g_start[NMAX];       // CSR row start (exclusive scan of cnt)
__device__ int   g_cursor[NMAX];      // fill cursors
__device__ int   g_srcs[1100000];     // CSR: source node per incoming edge
__device__ int   g_bsum[1024];        // scan block sums

// ---------------------------------------------------------------------------
// Degree / normalization
// ---------------------------------------------------------------------------
__global__ void k_count(const int* __restrict__ col, int* __restrict__ cnt, int E) {
    int e = blockIdx.x * blockDim.x + threadIdx.x;
    if (e < E) atomicAdd(&cnt[col[e]], 1);
}

__global__ void k_dinv(const int* __restrict__ cnt, float* __restrict__ dinv, int n) {
    int i = blockIdx.x * blockDim.x + threadIdx.x;
    if (i < n) dinv[i] = rsqrtf((float)(cnt[i] + 1));   // + self loop
}

// ---------------------------------------------------------------------------
// Exclusive prefix sum of cnt -> start (3-phase block scan)
// ---------------------------------------------------------------------------
__global__ void k_scan1(const int* __restrict__ cnt, int* __restrict__ startv,
                        int* __restrict__ bsum, int n) {
    __shared__ int sh[256];
    int t = threadIdx.x, i = blockIdx.x * 256 + t;
    int v = (i < n) ? cnt[i] : 0;
    sh[t] = v; __syncthreads();
    #pragma unroll
    for (int off = 1; off < 256; off <<= 1) {
        int x = (t >= off) ? sh[t - off] : 0;
        __syncthreads();
        sh[t] += x;
        __syncthreads();
    }
    if (i < n) startv[i] = sh[t] - v;           // block-local exclusive
    if (t == 255) bsum[blockIdx.x] = sh[255];   // block total
}

__global__ void k_scan2(int* __restrict__ bsum, int nb) {
    __shared__ int sh[512];
    int t = threadIdx.x;
    int v = (t < nb) ? bsum[t] : 0;
    sh[t] = v; __syncthreads();
    #pragma unroll
    for (int off = 1; off < 512; off <<= 1) {
        int x = (t >= off) ? sh[t - off] : 0;
        __syncthreads();
        sh[t] += x;
        __syncthreads();
    }
    if (t < nb) bsum[t] = sh[t] - v;            // exclusive
}

__global__ void k_scan3(int* __restrict__ startv, int* __restrict__ cursor,
                        const int* __restrict__ bsum, int n) {
    int i = blockIdx.x * blockDim.x + threadIdx.x;
    if (i < n) {
        int s = startv[i] + bsum[i >> 8];
        startv[i] = s;
        cursor[i] = s;
    }
}

__global__ void k_fill(const int* __restrict__ row, const int* __restrict__ col,
                       int* __restrict__ cursor, int* __restrict__ srcs, int E) {
    int e = blockIdx.x * blockDim.x + threadIdx.x;
    if (e < E) {
        int pos = atomicAdd(&cursor[col[e]], 1);
        srcs[pos] = row[e];
    }
}

// ---------------------------------------------------------------------------
// GEMM: Zs[r,:] = (X[r,:] @ W) * dinv[r]
//   64x64 block tile, 256 threads, 4x4 register tile/thread.
//   X tile stored k-major (transposed) in smem -> 2 LDS.128 per 16 FMA.
// ---------------------------------------------------------------------------
__global__ void k_gemm64(const float* __restrict__ X,
                         const float* __restrict__ W,
                         const float* __restrict__ dinv,
                         float* __restrict__ Z, int n) {
    __shared__ float Ws[64][64];     // Ws[k][col]
    __shared__ float Xst[64][68];    // Xst[k][row]  (stride 68: 16B-aligned quads)
    int t = threadIdx.x;
    int r0 = blockIdx.x * 64;

    #pragma unroll
    for (int i = t; i < 64 * 64; i += 256) Ws[i >> 6][i & 63] = W[i];

    #pragma unroll
    for (int q = t; q < 1024; q += 256) {       // 64 rows x 16 quads
        int r  = q >> 4;
        int c4 = (q & 15) * 4;
        int gr = r0 + r;
        float4 v = (gr < n) ? *reinterpret_cast<const float4*>(X + (size_t)gr * FD + c4)
                            : make_float4(0.f, 0.f, 0.f, 0.f);
        Xst[c4 + 0][r] = v.x; Xst[c4 + 1][r] = v.y;
        Xst[c4 + 2][r] = v.z; Xst[c4 + 3][r] = v.w;
    }
    __syncthreads();

    int tx = t & 15, ty = t >> 4;               // cols tx*4.., rows ty*4..
    float acc[4][4] = {};

    #pragma unroll
    for (int k = 0; k < 64; k++) {
        float4 xv = *reinterpret_cast<const float4*>(&Xst[k][ty * 4]);
        float4 wv = *reinterpret_cast<const float4*>(&Ws[k][tx * 4]);
        float xr[4] = {xv.x, xv.y, xv.z, xv.w};
        float wc[4] = {wv.x, wv.y, wv.z, wv.w};
        #pragma unroll
        for (int i = 0; i < 4; i++)
            #pragma unroll
            for (int j = 0; j < 4; j++)
                acc[i][j] = fmaf(xr[i], wc[j], acc[i][j]);
    }

    #pragma unroll
    for (int i = 0; i < 4; i++) {
        int gr = r0 + ty * 4 + i;
        if (gr < n) {
            float s = dinv[gr];
            float4 o = make_float4(acc[i][0] * s, acc[i][1] * s,
                                   acc[i][2] * s, acc[i][3] * s);
            *reinterpret_cast<float4*>(Z + (size_t)gr * FD + tx * 4) = o;
        }
    }
}

// ---------------------------------------------------------------------------
// Pull aggregation: out[c,:] = relu( (zs[c,:] + sum_{r->c} zs[r,:]) * dinv[c] + b )
//   One warp per node; float2 per lane; edge loop unrolled x4 for MLP.
// ---------------------------------------------------------------------------
__global__ void k_agg(const float* __restrict__ zs,
                      const int* __restrict__ srcs,
                      const int* __restrict__ startv,
                      const int* __restrict__ cnt,
                      const float* __restrict__ dinv,
                      const float* __restrict__ bias,
                      float* __restrict__ outp, int n) {
    int warp = (blockIdx.x * blockDim.x + threadIdx.x) >> 5;
    if (warp >= n) return;
    int lane = threadIdx.x & 31;

    const float2* zz = reinterpret_cast<const float2*>(zs);
    int s = startv[warp];
    int m = cnt[warp];
    float d = dinv[warp];

    float2 acc = zz[(size_t)warp * 32 + lane];          // self loop (zs = dinv*z)

    int i = 0;
    for (; i + 4 <= m; i += 4) {
        int r0 = srcs[s + i + 0];
        int r1 = srcs[s + i + 1];
        int r2 = srcs[s + i + 2];
        int r3 = srcs[s + i + 3];
        float2 v0 = zz[(size_t)r0 * 32 + lane];
        float2 v1 = zz[(size_t)r1 * 32 + lane];
        float2 v2 = zz[(size_t)r2 * 32 + lane];
        float2 v3 = zz[(size_t)r3 * 32 + lane];
        acc.x += (v0.x + v1.x) + (v2.x + v3.x);
        acc.y += (v0.y + v1.y) + (v2.y + v3.y);
    }
    for (; i < m; i++) {
        int r = srcs[s + i];
        float2 v = zz[(size_t)r * 32 + lane];
        acc.x += v.x; acc.y += v.y;
    }

    float2 b = reinterpret_cast<const float2*>(bias)[lane];
    float ox = fmaxf(fmaf(acc.x, d, b.x), 0.0f);
    float oy = fmaxf(fmaf(acc.y, d, b.y), 0.0f);
    reinterpret_cast<float2*>(outp)[(size_t)warp * 32 + lane] = make_float2(ox, oy);
}

// ---------------------------------------------------------------------------
// Launch
// ---------------------------------------------------------------------------
extern "C" void kernel_launch(void* const* d_in, const int* in_sizes, int n_in,
                              void* d_out, int out_size) {
    const float* x  = (const float*)d_in[0];
    const int*   ei = (const int*)d_in[1];
    const float* W1 = (const float*)d_in[2];
    const float* b1 = (const float*)d_in[3];
    const float* W2 = (const float*)d_in[4];
    const float* b2 = (const float*)d_in[5];
    float*       out = (float*)d_out;

    const int n = in_sizes[0] / FD;     // 100000
    const int E = in_sizes[1] / 2;      // 1000000
    const int* row = ei;
    const int* col = ei + E;

    float *z, *h, *dinv;
    int *cnt, *startv, *cursor, *srcs, *bsum;
    cudaGetSymbolAddress((void**)&z,      g_z);
    cudaGetSymbolAddress((void**)&h,      g_h);
    cudaGetSymbolAddress((void**)&dinv,   g_dinv);
    cudaGetSymbolAddress((void**)&cnt,    g_cnt);
    cudaGetSymbolAddress((void**)&startv, g_start);
    cudaGetSymbolAddress((void**)&cursor, g_cursor);
    cudaGetSymbolAddress((void**)&srcs,   g_srcs);
    cudaGetSymbolAddress((void**)&bsum,   g_bsum);

    const int T = 256;
    const int gN    = (n + T - 1) / T;          // 391
    const int gE    = (E + T - 1) / T;
    const int gGemm = (n + 63) / 64;
    const int gAgg  = (int)(((long long)n * 32 + T - 1) / T);

    // --- CSR build + normalization (once; reused by both layers) ---
    cudaMemsetAsync(cnt, 0, n * sizeof(int));
    k_count<<<gE, T>>>(col, cnt, E);
    k_dinv <<<gN, T>>>(cnt, dinv, n);
    k_scan1<<<gN, T>>>(cnt, startv, bsum, n);
    k_scan2<<<1, 512>>>(bsum, gN);
    k_scan3<<<gN, T>>>(startv, cursor, bsum, n);
    k_fill <<<gE, T>>>(row, col, cursor, srcs, E);

    // --- layer 1 ---
    k_gemm64<<<gGemm, T>>>(x, W1, dinv, z, n);
    k_agg   <<<gAgg, T>>>(z, srcs, startv, cnt, dinv, b1, h, n);

    // --- layer 2 ---
    k_gemm64<<<gGemm, T>>>(h, W2, dinv, z, n);
    k_agg   <<<gAgg, T>>>(z, srcs, startv, cnt, dinv, b2, out, n);
}

// round 8
// speedup vs baseline: 1.6555x; 1.0160x over previous
#include <cuda_runtime.h>
#include <cuda_fp16.h>
#include <math.h>

#define NMAX 100000
#define FD   64

// ---------------------------------------------------------------------------
// Scratch (__device__ globals; no allocation allowed)
// ---------------------------------------------------------------------------
__device__ __align__(256) __half g_z[NMAX * FD];   // dinv-scaled transformed feats (fp16)
__device__ __align__(256) float  g_h[NMAX * FD];   // layer-1 output (relu'd, fp32)
__device__ float g_dinv[NMAX];
__device__ int   g_cnt[NMAX];
__device__ int   g_start[NMAX];
__device__ int   g_cursor[NMAX];
__device__ int   g_srcs[1100000];
__device__ int   g_bsum[1024];

// ---------------------------------------------------------------------------
// Degree count
// ---------------------------------------------------------------------------
__global__ void k_count(const int* __restrict__ col, int* __restrict__ cnt, int E) {
    int e = blockIdx.x * blockDim.x + threadIdx.x;
    if (e < E) atomicAdd(&cnt[col[e]], 1);
}

// ---------------------------------------------------------------------------
// Scan phase 1 (+ dinv fused): block-local exclusive scan of cnt
// ---------------------------------------------------------------------------
__global__ void k_scan1(const int* __restrict__ cnt, int* __restrict__ startv,
                        int* __restrict__ bsum, float* __restrict__ dinv, int n) {
    __shared__ int sh[256];
    int t = threadIdx.x, i = blockIdx.x * 256 + t;
    int v = (i < n) ? cnt[i] : 0;
    if (i < n) dinv[i] = rsqrtf((float)(v + 1));   // + self loop
    sh[t] = v; __syncthreads();
    #pragma unroll
    for (int off = 1; off < 256; off <<= 1) {
        int x = (t >= off) ? sh[t - off] : 0;
        __syncthreads();
        sh[t] += x;
        __syncthreads();
    }
    if (i < n) startv[i] = sh[t] - v;
    if (t == 255) bsum[blockIdx.x] = sh[255];
}

// ---------------------------------------------------------------------------
// Scan phase 2: exclusive scan of block sums (shuffle-based, <=512 elems)
// ---------------------------------------------------------------------------
__global__ void k_scan2(int* __restrict__ bsum, int nb) {
    __shared__ int ws[16];
    int t = threadIdx.x, lane = t & 31, wid = t >> 5;
    int orig = (t < nb) ? bsum[t] : 0;
    int v = orig;
    #pragma unroll
    for (int off = 1; off < 32; off <<= 1) {
        int x = __shfl_up_sync(0xFFFFFFFFu, v, off);
        if (lane >= off) v += x;
    }
    if (lane == 31) ws[wid] = v;
    __syncthreads();
    if (wid == 0) {
        int w = (lane < 16) ? ws[lane] : 0;
        #pragma unroll
        for (int off = 1; off < 16; off <<= 1) {
            int x = __shfl_up_sync(0xFFFFFFFFu, w, off);
            if (lane >= off) w += x;
        }
        if (lane < 16) ws[lane] = w;   // inclusive warp sums
    }
    __syncthreads();
    int add = (wid > 0) ? ws[wid - 1] : 0;
    if (t < nb) bsum[t] = v + add - orig;   // exclusive
}

__global__ void k_scan3(int* __restrict__ startv, int* __restrict__ cursor,
                        const int* __restrict__ bsum, int n) {
    int i = blockIdx.x * blockDim.x + threadIdx.x;
    if (i < n) {
        int s = startv[i] + bsum[i >> 8];
        startv[i] = s;
        cursor[i] = s;
    }
}

__global__ void k_fill(const int* __restrict__ row, const int* __restrict__ col,
                       int* __restrict__ cursor, int* __restrict__ srcs, int E) {
    int e = blockIdx.x * blockDim.x + threadIdx.x;
    if (e < E) {
        int pos = atomicAdd(&cursor[col[e]], 1);
        srcs[pos] = row[e];
    }
}

// ---------------------------------------------------------------------------
// GEMM: Zh[r,:] = half( (X[r,:] @ W) * dinv[r] )
//   64x64 tile, 128 threads, 4 rows x 8 cols per thread.
//   Per k-iter: 3 x LDS.128 feeding 32 FMA.
// ---------------------------------------------------------------------------
__global__ void k_gemm64(const float* __restrict__ X,
                         const float* __restrict__ W,
                         const float* __restrict__ dinv,
                         __half* __restrict__ Z, int n) {
    __shared__ float Ws[64][64];     // Ws[k][col]
    __shared__ float Xst[64][68];    // Xst[k][row]
    int t = threadIdx.x;
    int r0 = blockIdx.x * 64;

    #pragma unroll
    for (int i = t; i < 1024; i += 128)
        reinterpret_cast<float4*>(Ws)[i] = reinterpret_cast<const float4*>(W)[i];

    #pragma unroll
    for (int q = t; q < 1024; q += 128) {       // 64 rows x 16 quads
        int r  = q >> 4;
        int c4 = (q & 15) * 4;
        int gr = r0 + r;
        float4 v = (gr < n) ? *reinterpret_cast<const float4*>(X + (size_t)gr * FD + c4)
                            : make_float4(0.f, 0.f, 0.f, 0.f);
        Xst[c4 + 0][r] = v.x; Xst[c4 + 1][r] = v.y;
        Xst[c4 + 2][r] = v.z; Xst[c4 + 3][r] = v.w;
    }
    __syncthreads();

    int tx = t & 7;          // col group: cols tx*8 .. tx*8+7
    int ty = t >> 3;         // row group: rows ty*4 .. ty*4+3
    float acc[4][8] = {};

    #pragma unroll
    for (int k = 0; k < 64; k++) {
        float4 xv  = *reinterpret_cast<const float4*>(&Xst[k][ty * 4]);
        float4 wva = *reinterpret_cast<const float4*>(&Ws[k][tx * 8]);
        float4 wvb = *reinterpret_cast<const float4*>(&Ws[k][tx * 8 + 4]);
        float xr[4] = {xv.x, xv.y, xv.z, xv.w};
        float wc[8] = {wva.x, wva.y, wva.z, wva.w, wvb.x, wvb.y, wvb.z, wvb.w};
        #pragma unroll
        for (int i = 0; i < 4; i++)
            #pragma unroll
            for (int j = 0; j < 8; j++)
                acc[i][j] = fmaf(xr[i], wc[j], acc[i][j]);
    }

    #pragma unroll
    for (int i = 0; i < 4; i++) {
        int gr = r0 + ty * 4 + i;
        if (gr < n) {
            float s = dinv[gr];
            __half2 hs[4];
            hs[0] = __floats2half2_rn(acc[i][0] * s, acc[i][1] * s);
            hs[1] = __floats2half2_rn(acc[i][2] * s, acc[i][3] * s);
            hs[2] = __floats2half2_rn(acc[i][4] * s, acc[i][5] * s);
            hs[3] = __floats2half2_rn(acc[i][6] * s, acc[i][7] * s);
            uint4 o = *reinterpret_cast<uint4*>(hs);
            *reinterpret_cast<uint4*>(Z + (size_t)gr * FD + tx * 8) = o;
        }
    }
}

// ---------------------------------------------------------------------------
// Pull aggregation (fp16 gathers, fp32 accum):
//   out[c,:] = relu( (zh[c,:] + sum_{r->c} zh[r,:]) * dinv[c] + b )
//   8 lanes per node, 16B (8 halves) per lane -> 1 x 128B wavefront per row.
// ---------------------------------------------------------------------------
__device__ __forceinline__ void acc_add8(float a[8], uint4 v) {
    __half2* p = reinterpret_cast<__half2*>(&v);
    #pragma unroll
    for (int q = 0; q < 4; q++) {
        float2 f = __half22float2(p[q]);
        a[q * 2 + 0] += f.x;
        a[q * 2 + 1] += f.y;
    }
}

__global__ void k_agg(const __half* __restrict__ zs,
                      const int* __restrict__ srcs,
                      const int* __restrict__ startv,
                      const int* __restrict__ cnt,
                      const float* __restrict__ dinv,
                      const float* __restrict__ bias,
                      float* __restrict__ outp, int n) {
    int tid  = blockIdx.x * blockDim.x + threadIdx.x;
    int node = tid >> 3;
    if (node >= n) return;
    int lane = tid & 7;

    const uint4* zq = reinterpret_cast<const uint4*>(zs);   // 16B = 8 halves
    int s = startv[node];
    int m = cnt[node];
    float d = dinv[node];

    float a[8] = {};
    acc_add8(a, zq[(size_t)node * 8 + lane]);   // self loop

    int i = 0;
    for (; i + 4 <= m; i += 4) {
        int r0 = srcs[s + i + 0];
        int r1 = srcs[s + i + 1];
        int r2 = srcs[s + i + 2];
        int r3 = srcs[s + i + 3];
        uint4 v0 = zq[(size_t)r0 * 8 + lane];
        uint4 v1 = zq[(size_t)r1 * 8 + lane];
        uint4 v2 = zq[(size_t)r2 * 8 + lane];
        uint4 v3 = zq[(size_t)r3 * 8 + lane];
        acc_add8(a, v0); acc_add8(a, v1);
        acc_add8(a, v2); acc_add8(a, v3);
    }
    for (; i < m; i++) {
        int r = srcs[s + i];
        acc_add8(a, zq[(size_t)r * 8 + lane]);
    }

    float4 b0 = reinterpret_cast<const float4*>(bias)[lane * 2 + 0];
    float4 b1 = reinterpret_cast<const float4*>(bias)[lane * 2 + 1];
    float4 o0 = make_float4(fmaxf(fmaf(a[0], d, b0.x), 0.f),
                            fmaxf(fmaf(a[1], d, b0.y), 0.f),
                            fmaxf(fmaf(a[2], d, b0.z), 0.f),
                            fmaxf(fmaf(a[3], d, b0.w), 0.f));
    float4 o1 = make_float4(fmaxf(fmaf(a[4], d, b1.x), 0.f),
                            fmaxf(fmaf(a[5], d, b1.y), 0.f),
                            fmaxf(fmaf(a[6], d, b1.z), 0.f),
                            fmaxf(fmaf(a[7], d, b1.w), 0.f));
    float4* po = reinterpret_cast<float4*>(outp + (size_t)node * FD + lane * 8);
    po[0] = o0;
    po[1] = o1;
}

// ---------------------------------------------------------------------------
// Launch
// ---------------------------------------------------------------------------
extern "C" void kernel_launch(void* const* d_in, const int* in_sizes, int n_in,
                              void* d_out, int out_size) {
    const float* x  = (const float*)d_in[0];
    const int*   ei = (const int*)d_in[1];
    const float* W1 = (const float*)d_in[2];
    const float* b1 = (const float*)d_in[3];
    const float* W2 = (const float*)d_in[4];
    const float* b2 = (const float*)d_in[5];
    float*       out = (float*)d_out;

    const int n = in_sizes[0] / FD;     // 100000
    const int E = in_sizes[1] / 2;      // 1000000
    const int* row = ei;
    const int* col = ei + E;

    __half* z; float *h, *dinv;
    int *cnt, *startv, *cursor, *srcs, *bsum;
    cudaGetSymbolAddress((void**)&z,      g_z);
    cudaGetSymbolAddress((void**)&h,      g_h);
    cudaGetSymbolAddress((void**)&dinv,   g_dinv);
    cudaGetSymbolAddress((void**)&cnt,    g_cnt);
    cudaGetSymbolAddress((void**)&startv, g_start);
    cudaGetSymbolAddress((void**)&cursor, g_cursor);
    cudaGetSymbolAddress((void**)&srcs,   g_srcs);
    cudaGetSymbolAddress((void**)&bsum,   g_bsum);

    const int T = 256;
    const int gN    = (n + T - 1) / T;          // 391
    const int gE    = (E + T - 1) / T;
    const int gGemm = (n + 63) / 64;
    const int gAgg  = (int)(((long long)n * 8 + T - 1) / T);

    // --- CSR build + normalization ---
    cudaMemsetAsync(cnt, 0, n * sizeof(int));
    k_count<<<gE, T>>>(col, cnt, E);
    k_scan1<<<gN, T>>>(cnt, startv, bsum, dinv, n);
    k_scan2<<<1, 512>>>(bsum, gN);
    k_scan3<<<gN, T>>>(startv, cursor, bsum, n);
    k_fill <<<gE, T>>>(row, col, cursor, srcs, E);

    // --- layer 1 ---
    k_gemm64<<<gGemm, 128>>>(x, W1, dinv, z, n);
    k_agg   <<<gAgg, T>>>(z, srcs, startv, cnt, dinv, b1, h, n);

    // --- layer 2 ---
    k_gemm64<<<gGemm, 128>>>(h, W2, dinv, z, n);
    k_agg   <<<gAgg, T>>>(z, srcs, startv, cnt, dinv, b2, out, n);
}